// round 4
// baseline (speedup 1.0000x reference)
#include <cuda_runtime.h>
#include <cstdint>

// InversePixelShuffle (pixel_unshuffle, k=2)
// in : (B=8, C=32, H=512, W=512) fp32
// out: (B=8, 128, 256, 256) fp32
// out[b, c*4 + y*2 + x, ho, wo] = in[b, c, 2*ho + y, 2*wo + x]
//
// R2 structure (best DRAM% so far), plus streaming cache hints:
//   warp <-> one input row. Lane l loads float4 pairs (2l,2l+1) and
//   (64+2l,65+2l); consecutive pairs deinterleave in registers into one
//   float4 of even-w (channel co) and one of odd-w (channel co+1) at
//   output row ho = h/2. Loads via __ldcs, stores via __stcs: both
//   streams are touch-once, so evict-first policy lets L2 retire dirty
//   write sectors promptly and keeps read/write DRAM bursts cleaner.

static constexpr unsigned H_IN        = 512;
static constexpr unsigned NUM_ROWS    = 8u * 32u * 512u;  // 131072 warps
static constexpr unsigned OUT_CH_F4   = 256u * 256u / 4u; // 16384
static constexpr unsigned OUT_ROW_F4  = 256u / 4u;        // 64

__global__ void __launch_bounds__(256)
inverse_pixel_shuffle_kernel(const float4* __restrict__ in,
                             float4* __restrict__ out) {
    unsigned tid  = blockIdx.x * blockDim.x + threadIdx.x;
    unsigned lane = tid & 31u;
    unsigned wid  = tid >> 5;                 // one warp per input row

    unsigned h  = wid & (H_IN - 1);
    unsigned bc = wid >> 9;                   // b*32 + c

    const float4* inrow = in + ((size_t)wid << 7);   // wid * 128 float4
    unsigned l2 = 2u * lane;

    // Four independent streaming loads (evict-first).
    float4 a0 = __ldcs(inrow + l2);
    float4 a1 = __ldcs(inrow + l2 + 1u);
    float4 b0 = __ldcs(inrow + 64u + l2);
    float4 b1 = __ldcs(inrow + 64u + l2 + 1u);

    unsigned ho = h >> 1;
    unsigned y  = h & 1u;
    unsigned co = bc * 4u + y * 2u;           // b*128 + c*4 + 2y

    float4* orow = out + ((size_t)co * 256u + ho) * OUT_ROW_F4;

    // Even-w elements -> channel co ; odd-w -> channel co+1.
    __stcs(orow + lane,                  make_float4(a0.x, a0.z, a1.x, a1.z));
    __stcs(orow + 32u + lane,            make_float4(b0.x, b0.z, b1.x, b1.z));
    __stcs(orow + OUT_CH_F4 + lane,      make_float4(a0.y, a0.w, a1.y, a1.w));
    __stcs(orow + OUT_CH_F4 + 32u + lane, make_float4(b0.y, b0.w, b1.y, b1.w));
}

extern "C" void kernel_launch(void* const* d_in, const int* in_sizes, int n_in,
                              void* d_out, int out_size) {
    const float4* in  = (const float4*)d_in[0];
    float4*       out = (float4*)d_out;

    const unsigned threads = 256;                         // 8 warps = 8 rows/block
    const unsigned blocks  = (NUM_ROWS * 32u) / threads;  // 16384
    inverse_pixel_shuffle_kernel<<<blocks, threads>>>(in, out);
}